// round 4
// baseline (speedup 1.0000x reference)
#include <cuda_runtime.h>
#include <math.h>

#define NB   4
#define NL   2048
#define ND   512
#define NH   8
#define NDK  64
#define NM   (NB*NL)   /* 8192 */

// Scratch (static __device__ arrays — allocation-free per harness rules)
__device__ float g_Q[NM*ND];    // (B,H,L,dk)
__device__ float g_K[NM*ND];    // (B,H,L,dk)
__device__ float g_V[NM*ND];    // (B,H,L,dk)
__device__ float g_att[NM*ND];  // (B,L,D)

// ---------------------------------------------------------------------------
// GEMM: Y = X @ W^T.  X: (NM, 512) row-major, W: (512, 512) row-major.
// mode 0: Y[m*512 + n]   (plain row-major)
// mode 1: Y laid out (B,H,L,dk): ((b*8+h)*2048 + l)*64 + d,  b=m>>11, l=m&2047,
//         h=n>>6, d=n&63
// ---------------------------------------------------------------------------
__global__ __launch_bounds__(256)
void gemm_xwT(const float* __restrict__ X, const float* __restrict__ W,
              float* __restrict__ Y, int mode)
{
    __shared__ float Xs[64][17];   // [row][k], pad 17 (conflict-free scalar reads)
    __shared__ float Ws[16][68];   // transposed: [k][n], pad 68 (16B-aligned rows)

    const int tx = threadIdx.x, ty = threadIdx.y;
    const int tid = ty * 16 + tx;
    const int m0 = blockIdx.y * 64, n0 = blockIdx.x * 64;

    const int lr = tid >> 2;         // 0..63  (row / W-row)
    const int lk = (tid & 3) * 4;    // 0,4,8,12

    float acc[4][4] = {};

    for (int k0 = 0; k0 < 512; k0 += 16) {
        float4 xa = *(const float4*)&X[(size_t)(m0 + lr) * 512 + k0 + lk];
        float4 wa = *(const float4*)&W[(size_t)(n0 + lr) * 512 + k0 + lk];
        Xs[lr][lk + 0] = xa.x; Xs[lr][lk + 1] = xa.y;
        Xs[lr][lk + 2] = xa.z; Xs[lr][lk + 3] = xa.w;
        Ws[lk + 0][lr] = wa.x; Ws[lk + 1][lr] = wa.y;
        Ws[lk + 2][lr] = wa.z; Ws[lk + 3][lr] = wa.w;
        __syncthreads();

        #pragma unroll
        for (int kk = 0; kk < 16; kk++) {
            float4 b4 = *(const float4*)&Ws[kk][tx * 4];
            float a0 = Xs[ty * 4 + 0][kk];
            float a1 = Xs[ty * 4 + 1][kk];
            float a2 = Xs[ty * 4 + 2][kk];
            float a3 = Xs[ty * 4 + 3][kk];
            acc[0][0] += a0 * b4.x; acc[0][1] += a0 * b4.y;
            acc[0][2] += a0 * b4.z; acc[0][3] += a0 * b4.w;
            acc[1][0] += a1 * b4.x; acc[1][1] += a1 * b4.y;
            acc[1][2] += a1 * b4.z; acc[1][3] += a1 * b4.w;
            acc[2][0] += a2 * b4.x; acc[2][1] += a2 * b4.y;
            acc[2][2] += a2 * b4.z; acc[2][3] += a2 * b4.w;
            acc[3][0] += a3 * b4.x; acc[3][1] += a3 * b4.y;
            acc[3][2] += a3 * b4.z; acc[3][3] += a3 * b4.w;
        }
        __syncthreads();
    }

    #pragma unroll
    for (int i = 0; i < 4; i++) {
        int m = m0 + ty * 4 + i;
        float4 v = make_float4(acc[i][0], acc[i][1], acc[i][2], acc[i][3]);
        if (mode == 0) {
            *(float4*)&Y[(size_t)m * 512 + n0 + tx * 4] = v;
        } else {
            int b = m >> 11, l = m & 2047, h = n0 >> 6;
            *(float4*)&Y[((size_t)((b * 8 + h) * 2048 + l)) * 64 + tx * 4] = v;
        }
    }
}

// ---------------------------------------------------------------------------
// Wave attention: per block, 64 query rows of one (b,h); stream K/V in
// 64-row tiles; online softmax with wave modulation.
// 256 threads: qi = tid>>2 (query row), sub = tid&3.
//   - scores: thread owns k-cols kc = sub + 4*jj (jj 0..15)
//   - output: thread owns dim float4-chunks at 4*(sub + 4*jv) (jv 0..3)
// Dynamic smem: Qs/Ks/Vs/Ps each [64][68] floats = 69632 B total.
// ---------------------------------------------------------------------------
#define SMEM_ATTN (4 * 64 * 68 * 4)

__global__ __launch_bounds__(256)
void wave_attn(const float* __restrict__ wfreq, const float* __restrict__ wphase)
{
    extern __shared__ float sm[];
    float* Qs = sm;                 // [64][68]
    float* Ks = sm + 64 * 68;       // [64][68]
    float* Vs = sm + 2 * 64 * 68;   // [64][68]
    float* Ps = sm + 3 * 64 * 68;   // [64][68]

    const int tid = threadIdx.x;
    const int bh  = blockIdx.y;       // 0..31
    const int b   = bh >> 3, h = bh & 7;
    const int q0  = blockIdx.x * 64;

    const float freq  = wfreq[h];
    const float phase = wphase[h];
    const float TWO_PI = 6.28318530717958647692f;

    const float* Qg = g_Q + ((size_t)bh * NL + q0) * NDK;
    const float* Kg = g_K + (size_t)bh * NL * NDK;
    const float* Vg = g_V + (size_t)bh * NL * NDK;

    // Load Q tile (scaled by dk^-1/2 = 0.125)
    #pragma unroll
    for (int i = 0; i < 4; i++) {
        int idx = tid + 256 * i;          // 0..1023 float4 slots
        int r = idx >> 4, c = (idx & 15) * 4;
        float4 v = *(const float4*)&Qg[r * 64 + c];
        v.x *= 0.125f; v.y *= 0.125f; v.z *= 0.125f; v.w *= 0.125f;
        *(float4*)&Qs[r * 68 + c] = v;
    }

    const int qi = tid >> 2, sub = tid & 3;
    float m = -1e30f, lsum = 0.f;
    float o[16];
    #pragma unroll
    for (int t = 0; t < 16; t++) o[t] = 0.f;

    for (int kt = 0; kt < 32; kt++) {
        // Load K/V tiles (coalesced float4)
        #pragma unroll
        for (int i = 0; i < 4; i++) {
            int idx = tid + 256 * i;
            int r = idx >> 4, c = (idx & 15) * 4;
            *(float4*)&Ks[r * 68 + c] = *(const float4*)&Kg[(size_t)(kt * 64 + r) * 64 + c];
            *(float4*)&Vs[r * 68 + c] = *(const float4*)&Vg[(size_t)(kt * 64 + r) * 64 + c];
        }
        __syncthreads();

        // Scores for this thread's 16 k-columns
        float s[16];
        #pragma unroll
        for (int jj = 0; jj < 16; jj++) s[jj] = 0.f;
        #pragma unroll
        for (int d0 = 0; d0 < 64; d0 += 4) {
            float4 q4 = *(const float4*)&Qs[qi * 68 + d0];
            #pragma unroll
            for (int jj = 0; jj < 16; jj++) {
                int kc = sub + 4 * jj;
                float4 k4 = *(const float4*)&Ks[kc * 68 + d0];
                s[jj] += q4.x * k4.x + q4.y * k4.y + q4.z * k4.z + q4.w * k4.w;
            }
        }
        // Wave modulation (applied after dot; scale was folded into Q)
        #pragma unroll
        for (int jj = 0; jj < 16; jj++) {
            float kpos = (float)(kt * 64 + sub + 4 * jj);
            s[jj] *= cosf(TWO_PI * freq * kpos + phase);
        }

        // Tile max across this thread + its 3 row-partners (consecutive lanes)
        float tm = s[0];
        #pragma unroll
        for (int jj = 1; jj < 16; jj++) tm = fmaxf(tm, s[jj]);
        tm = fmaxf(tm, __shfl_xor_sync(0xffffffffu, tm, 1));
        tm = fmaxf(tm, __shfl_xor_sync(0xffffffffu, tm, 2));

        float mn = fmaxf(m, tm);
        float scale = __expf(m - mn);
        float psum = 0.f;
        #pragma unroll
        for (int jj = 0; jj < 16; jj++) {
            s[jj] = __expf(s[jj] - mn);
            psum += s[jj];
        }
        psum += __shfl_xor_sync(0xffffffffu, psum, 1);
        psum += __shfl_xor_sync(0xffffffffu, psum, 2);
        lsum = lsum * scale + psum;
        m = mn;
        #pragma unroll
        for (int t = 0; t < 16; t++) o[t] *= scale;

        // Share probabilities within the 4-thread row group (same warp)
        #pragma unroll
        for (int jj = 0; jj < 16; jj++)
            Ps[qi * 68 + sub + 4 * jj] = s[jj];
        __syncwarp();

        // O += P @ V  (thread's dims: float4 chunks at 4*(sub+4*jv))
        #pragma unroll
        for (int k0 = 0; k0 < 64; k0 += 4) {
            float p4[4];
            *(float4*)p4 = *(const float4*)&Ps[qi * 68 + k0];
            #pragma unroll
            for (int kk = 0; kk < 4; kk++) {
                float pv = p4[kk];
                #pragma unroll
                for (int jv = 0; jv < 4; jv++) {
                    float4 v4 = *(const float4*)&Vs[(k0 + kk) * 68 + 4 * (sub + 4 * jv)];
                    o[jv * 4 + 0] += pv * v4.x;
                    o[jv * 4 + 1] += pv * v4.y;
                    o[jv * 4 + 2] += pv * v4.z;
                    o[jv * 4 + 3] += pv * v4.w;
                }
            }
        }
        __syncthreads();
    }

    // Epilogue: normalize and write to (B,L,D) layout
    float inv = 1.f / lsum;
    size_t row = ((size_t)b * NL + q0 + qi) * ND + h * NDK;
    #pragma unroll
    for (int jv = 0; jv < 4; jv++) {
        float4 v = make_float4(o[jv * 4 + 0] * inv, o[jv * 4 + 1] * inv,
                               o[jv * 4 + 2] * inv, o[jv * 4 + 3] * inv);
        *(float4*)&g_att[row + 4 * (sub + 4 * jv)] = v;
    }
}

// ---------------------------------------------------------------------------
extern "C" void kernel_launch(void* const* d_in, const int* in_sizes, int n_in,
                              void* d_out, int out_size)
{
    (void)in_sizes; (void)n_in; (void)out_size;
    const float* x  = (const float*)d_in[0];
    const float* Wq = (const float*)d_in[1];
    const float* Wk = (const float*)d_in[2];
    const float* Wv = (const float*)d_in[3];
    const float* Wo = (const float*)d_in[4];
    const float* wf = (const float*)d_in[5];
    const float* wp = (const float*)d_in[6];
    float* out = (float*)d_out;

    float *Qp, *Kp, *Vp, *Ap;
    cudaGetSymbolAddress((void**)&Qp, g_Q);
    cudaGetSymbolAddress((void**)&Kp, g_K);
    cudaGetSymbolAddress((void**)&Vp, g_V);
    cudaGetSymbolAddress((void**)&Ap, g_att);

    dim3 gblk(16, 16);
    dim3 ggrid(8, 128);   // (N/64, M/64)

    gemm_xwT<<<ggrid, gblk>>>(x, Wq, Qp, 1);
    gemm_xwT<<<ggrid, gblk>>>(x, Wk, Kp, 1);
    gemm_xwT<<<ggrid, gblk>>>(x, Wv, Vp, 1);

    cudaFuncSetAttribute(wave_attn, cudaFuncAttributeMaxDynamicSharedMemorySize, SMEM_ATTN);
    wave_attn<<<dim3(32, 32), 256, SMEM_ATTN>>>(wf, wp);

    gemm_xwT<<<ggrid, gblk>>>(Ap, Wo, out, 0);
}

// round 5
// speedup vs baseline: 4.6856x; 4.6856x over previous
#include <cuda_runtime.h>
#include <math.h>

#define NB   4
#define NL   2048
#define ND   512
#define NH   8
#define NDK  64
#define NM   (NB*NL)   /* 8192 */

// Scratch (static __device__ arrays — allocation-free per harness rules)
__device__ float g_Q[NM*ND];    // (B,H,L,dk)
__device__ float g_K[NM*ND];    // (B,H,L,dk)
__device__ float g_V[NM*ND];    // (B,H,L,dk)
__device__ float g_att[NM*ND];  // (B,L,D)

// ---------------------------------------------------------------------------
// TF32 helpers
// ---------------------------------------------------------------------------
__device__ __forceinline__ unsigned f2tf(float f) {
    unsigned u;
    asm("cvt.rna.tf32.f32 %0, %1;" : "=r"(u) : "f"(f));
    return u;
}

// D(16x8) += A(16x8) * B(8x8), tf32 inputs, fp32 accumulate.
// Lane mapping (g = lane>>2, t = lane&3):
//  A: a0=(g,t) a1=(g+8,t) a2=(g,t+4) a3=(g+8,t+4)   [row, k]
//  B: b0=(t,g) b1=(t+4,g)                            [k, n]
//  D: c0=(g,2t) c1=(g,2t+1) c2=(g+8,2t) c3=(g+8,2t+1)
__device__ __forceinline__ void mma8(float* d, const unsigned* a, const unsigned* b) {
    asm volatile("mma.sync.aligned.m16n8k8.row.col.f32.tf32.tf32.f32 "
                 "{%0,%1,%2,%3}, {%4,%5,%6,%7}, {%8,%9}, {%0,%1,%2,%3};"
                 : "+f"(d[0]), "+f"(d[1]), "+f"(d[2]), "+f"(d[3])
                 : "r"(a[0]), "r"(a[1]), "r"(a[2]), "r"(a[3]),
                   "r"(b[0]), "r"(b[1]));
}

// ---------------------------------------------------------------------------
// GEMM (tensor): Y = X @ W^T.  X: (NM,512), W: (512,512), row-major fp32.
// Block tile 128(m) x 64(n), K-chunk 32. 8 warps in 4(m) x 2(n) layout,
// each warp 32x32 (2 m-tiles x 4 n-tiles of m16n8k8).
// mode 0: Y[m*512+n]; mode 1: (B,H,L,dk) scatter, h = blockIdx.x.
// ---------------------------------------------------------------------------
#define XS_ST 36
#define WS_ST 36

__global__ __launch_bounds__(256)
void gemm_tc(const float* __restrict__ X, const float* __restrict__ W,
             float* __restrict__ Y, int mode)
{
    __shared__ float Xs[128 * XS_ST];
    __shared__ float Ws[64 * WS_ST];

    const int tid  = threadIdx.x;
    const int w    = tid >> 5, lane = tid & 31;
    const int g    = lane >> 2, t = lane & 3;
    const int wm   = w & 3, wn = w >> 2;
    const int m0   = blockIdx.y * 128, n0 = blockIdx.x * 64;

    float acc[2][4][4];
    #pragma unroll
    for (int mt = 0; mt < 2; mt++)
        #pragma unroll
        for (int nt = 0; nt < 4; nt++)
            #pragma unroll
            for (int i = 0; i < 4; i++) acc[mt][nt][i] = 0.f;

    for (int k0 = 0; k0 < 512; k0 += 32) {
        // Stage X tile (128x32) as tf32
        #pragma unroll
        for (int i = 0; i < 4; i++) {
            int idx = tid + 256 * i;            // 1024 float4 slots
            int r = idx >> 3, c = (idx & 7) * 4;
            float4 v = *(const float4*)&X[(size_t)(m0 + r) * 512 + k0 + c];
            float4 o = make_float4(__uint_as_float(f2tf(v.x)), __uint_as_float(f2tf(v.y)),
                                   __uint_as_float(f2tf(v.z)), __uint_as_float(f2tf(v.w)));
            *(float4*)&Xs[r * XS_ST + c] = o;
        }
        // Stage W tile (64x32) as tf32
        #pragma unroll
        for (int i = 0; i < 2; i++) {
            int idx = tid + 256 * i;            // 512 float4 slots
            int r = idx >> 3, c = (idx & 7) * 4;
            float4 v = *(const float4*)&W[(size_t)(n0 + r) * 512 + k0 + c];
            float4 o = make_float4(__uint_as_float(f2tf(v.x)), __uint_as_float(f2tf(v.y)),
                                   __uint_as_float(f2tf(v.z)), __uint_as_float(f2tf(v.w)));
            *(float4*)&Ws[r * WS_ST + c] = o;
        }
        __syncthreads();

        #pragma unroll
        for (int ks = 0; ks < 4; ks++) {
            unsigned a[2][4], bb[4][2];
            #pragma unroll
            for (int mt = 0; mt < 2; mt++) {
                const float* p = &Xs[(wm * 32 + mt * 16 + g) * XS_ST + ks * 8 + t];
                a[mt][0] = __float_as_uint(p[0]);
                a[mt][1] = __float_as_uint(p[8 * XS_ST]);
                a[mt][2] = __float_as_uint(p[4]);
                a[mt][3] = __float_as_uint(p[8 * XS_ST + 4]);
            }
            #pragma unroll
            for (int nt = 0; nt < 4; nt++) {
                const float* p = &Ws[(wn * 32 + nt * 8 + g) * WS_ST + ks * 8 + t];
                bb[nt][0] = __float_as_uint(p[0]);
                bb[nt][1] = __float_as_uint(p[4]);
            }
            #pragma unroll
            for (int mt = 0; mt < 2; mt++)
                #pragma unroll
                for (int nt = 0; nt < 4; nt++)
                    mma8(acc[mt][nt], a[mt], bb[nt]);
        }
        __syncthreads();
    }

    // Epilogue
    #pragma unroll
    for (int mt = 0; mt < 2; mt++) {
        int row = m0 + wm * 32 + mt * 16 + g;
        #pragma unroll
        for (int nt = 0; nt < 4; nt++) {
            int off = wn * 32 + nt * 8 + 2 * t;      // 0..63 within n-block
            float2 v0 = make_float2(acc[mt][nt][0], acc[mt][nt][1]);
            float2 v1 = make_float2(acc[mt][nt][2], acc[mt][nt][3]);
            if (mode == 0) {
                float* p = &Y[(size_t)row * 512 + n0 + off];
                *(float2*)p = v0;
                *(float2*)(p + (size_t)8 * 512) = v1;
            } else {
                int b = row >> 11, l = row & 2047, h = blockIdx.x;
                size_t base = ((size_t)((b * 8 + h) * 2048 + l)) * 64 + off;
                *(float2*)&Y[base] = v0;
                *(float2*)&Y[base + (size_t)8 * 64] = v1;
            }
        }
    }
}

// ---------------------------------------------------------------------------
// Wave attention (tensor): 64 q-rows per block, 4 warps (16 rows each),
// stream 64-key tiles; S=QK^T and O+=PV via tf32 mma; online softmax fp32.
// Smem: Ks[64][68], Vs[64][72], Ps[64][68], wave[2048]  (61440 B)
// ---------------------------------------------------------------------------
#define KS_ST 68
#define VS_ST 72
#define PS_ST 68
#define SM_V   (64 * KS_ST)
#define SM_P   (SM_V + 64 * VS_ST)
#define SM_WAVE (SM_P + 64 * PS_ST)
#define SMEM_ATTN ((SM_WAVE + 2048) * 4)

__global__ __launch_bounds__(128)
void wave_attn_tc(const float* __restrict__ wfreq, const float* __restrict__ wphase)
{
    extern __shared__ float sm[];
    float* Ks = sm;
    float* Vs = sm + SM_V;
    float* Ps = sm + SM_P;
    float* Wv = sm + SM_WAVE;

    const int tid = threadIdx.x;
    const int w   = tid >> 5, lane = tid & 31;
    const int g   = lane >> 2, t = lane & 3;
    const int bh  = blockIdx.y, b = bh >> 3, h = bh & 7;
    const int q0  = blockIdx.x * 64;
    const int rb  = w * 16 + g;          // this thread's first row in the q-tile

    const float* Qg = g_Q + ((size_t)bh * NL + q0) * NDK;
    const float* Kg = g_K + (size_t)bh * NL * NDK;
    const float* Vg = g_V + (size_t)bh * NL * NDK;

    // Wave table (once per block)
    {
        const float f = wfreq[h], ph = wphase[h];
        const float TWO_PI = 6.28318530717958647692f;
        for (int j = tid; j < NL; j += 128)
            Wv[j] = cosf(TWO_PI * f * (float)j + ph);
    }

    // Stage Q (scaled by dk^-1/2) into Ks, then lift A-fragments to registers
    #pragma unroll
    for (int i = 0; i < 8; i++) {
        int idx = tid + 128 * i;             // 1024 float4 slots
        int r = idx >> 4, c = (idx & 15) * 4;
        float4 v = *(const float4*)&Qg[r * 64 + c];
        v.x *= 0.125f; v.y *= 0.125f; v.z *= 0.125f; v.w *= 0.125f;
        *(float4*)&Ks[r * KS_ST + c] = v;
    }
    __syncthreads();

    unsigned Qa[8][4];
    #pragma unroll
    for (int ks = 0; ks < 8; ks++) {
        const float* p = &Ks[rb * KS_ST + ks * 8 + t];
        Qa[ks][0] = f2tf(p[0]);
        Qa[ks][1] = f2tf(p[8 * KS_ST]);
        Qa[ks][2] = f2tf(p[4]);
        Qa[ks][3] = f2tf(p[8 * KS_ST + 4]);
    }
    __syncthreads();   // done with Ks as Q staging

    float Oc[8][4];
    #pragma unroll
    for (int nt = 0; nt < 8; nt++)
        #pragma unroll
        for (int i = 0; i < 4; i++) Oc[nt][i] = 0.f;
    float mA = -1e30f, mB = -1e30f, lA = 0.f, lB = 0.f;

    for (int kt = 0; kt < 32; kt++) {
        // Stage K and V tiles (tf32)
        #pragma unroll
        for (int i = 0; i < 8; i++) {
            int idx = tid + 128 * i;
            int r = idx >> 4, c = (idx & 15) * 4;
            float4 kv = *(const float4*)&Kg[(size_t)(kt * 64 + r) * 64 + c];
            float4 vv = *(const float4*)&Vg[(size_t)(kt * 64 + r) * 64 + c];
            float4 ko = make_float4(__uint_as_float(f2tf(kv.x)), __uint_as_float(f2tf(kv.y)),
                                    __uint_as_float(f2tf(kv.z)), __uint_as_float(f2tf(kv.w)));
            float4 vo = make_float4(__uint_as_float(f2tf(vv.x)), __uint_as_float(f2tf(vv.y)),
                                    __uint_as_float(f2tf(vv.z)), __uint_as_float(f2tf(vv.w)));
            *(float4*)&Ks[r * KS_ST + c] = ko;
            *(float4*)&Vs[r * VS_ST + c] = vo;
        }
        __syncthreads();

        // S = Q @ K^T (warp rows rb.., all 64 key cols)
        float Sc[8][4];
        #pragma unroll
        for (int nt = 0; nt < 8; nt++)
            #pragma unroll
            for (int i = 0; i < 4; i++) Sc[nt][i] = 0.f;
        #pragma unroll
        for (int ks = 0; ks < 8; ks++) {
            #pragma unroll
            for (int nt = 0; nt < 8; nt++) {
                unsigned bb[2];
                const float* p = &Ks[(nt * 8 + g) * KS_ST + ks * 8 + t];
                bb[0] = __float_as_uint(p[0]);
                bb[1] = __float_as_uint(p[4]);
                mma8(Sc[nt], Qa[ks], bb);
            }
        }

        // Wave modulation + running max (rows rb -> A, rb+8 -> B)
        float nmA = mA, nmB = mB;
        #pragma unroll
        for (int nt = 0; nt < 8; nt++) {
            int col = kt * 64 + nt * 8 + 2 * t;
            float w0 = Wv[col & (NL - 1)], w1 = Wv[(col + 1) & (NL - 1)];
            Sc[nt][0] *= w0; Sc[nt][1] *= w1;
            Sc[nt][2] *= w0; Sc[nt][3] *= w1;
            nmA = fmaxf(nmA, fmaxf(Sc[nt][0], Sc[nt][1]));
            nmB = fmaxf(nmB, fmaxf(Sc[nt][2], Sc[nt][3]));
        }
        nmA = fmaxf(nmA, __shfl_xor_sync(0xffffffffu, nmA, 1));
        nmB = fmaxf(nmB, __shfl_xor_sync(0xffffffffu, nmB, 1));
        nmA = fmaxf(nmA, __shfl_xor_sync(0xffffffffu, nmA, 2));
        nmB = fmaxf(nmB, __shfl_xor_sync(0xffffffffu, nmB, 2));

        float scA = __expf(mA - nmA), scB = __expf(mB - nmB);
        mA = nmA; mB = nmB;

        float psA = 0.f, psB = 0.f;
        #pragma unroll
        for (int nt = 0; nt < 8; nt++) {
            float p0 = __expf(Sc[nt][0] - mA);
            float p1 = __expf(Sc[nt][1] - mA);
            float p2 = __expf(Sc[nt][2] - mB);
            float p3 = __expf(Sc[nt][3] - mB);
            psA += p0 + p1; psB += p2 + p3;
            int cb = nt * 8 + 2 * t;
            Ps[rb * PS_ST + cb]           = __uint_as_float(f2tf(p0));
            Ps[rb * PS_ST + cb + 1]       = __uint_as_float(f2tf(p1));
            Ps[(rb + 8) * PS_ST + cb]     = __uint_as_float(f2tf(p2));
            Ps[(rb + 8) * PS_ST + cb + 1] = __uint_as_float(f2tf(p3));
        }
        psA += __shfl_xor_sync(0xffffffffu, psA, 1);
        psB += __shfl_xor_sync(0xffffffffu, psB, 1);
        psA += __shfl_xor_sync(0xffffffffu, psA, 2);
        psB += __shfl_xor_sync(0xffffffffu, psB, 2);
        lA = lA * scA + psA;
        lB = lB * scB + psB;

        #pragma unroll
        for (int nt = 0; nt < 8; nt++) {
            Oc[nt][0] *= scA; Oc[nt][1] *= scA;
            Oc[nt][2] *= scB; Oc[nt][3] *= scB;
        }
        __syncwarp();   // P rows rb..rb+15 are warp-private

        // O += P @ V
        #pragma unroll
        for (int ks = 0; ks < 8; ks++) {
            unsigned pa[4];
            const float* pp = &Ps[rb * PS_ST + ks * 8 + t];
            pa[0] = __float_as_uint(pp[0]);
            pa[1] = __float_as_uint(pp[8 * PS_ST]);
            pa[2] = __float_as_uint(pp[4]);
            pa[3] = __float_as_uint(pp[8 * PS_ST + 4]);
            #pragma unroll
            for (int nt = 0; nt < 8; nt++) {
                unsigned bb[2];
                const float* vp = &Vs[(ks * 8 + t) * VS_ST + nt * 8 + g];
                bb[0] = __float_as_uint(vp[0]);
                bb[1] = __float_as_uint(vp[4 * VS_ST]);
                mma8(Oc[nt], pa, bb);
            }
        }
        __syncthreads();   // before next tile overwrites Ks/Vs
    }

    // Epilogue: normalize, write (B,L,D)
    float iA = 1.f / lA, iB = 1.f / lB;
    size_t baseA = ((size_t)b * NL + q0 + rb) * ND + h * NDK;
    size_t baseB = baseA + (size_t)8 * ND;
    #pragma unroll
    for (int nt = 0; nt < 8; nt++) {
        int cb = nt * 8 + 2 * t;
        *(float2*)&g_att[baseA + cb] = make_float2(Oc[nt][0] * iA, Oc[nt][1] * iA);
        *(float2*)&g_att[baseB + cb] = make_float2(Oc[nt][2] * iB, Oc[nt][3] * iB);
    }
}

// ---------------------------------------------------------------------------
extern "C" void kernel_launch(void* const* d_in, const int* in_sizes, int n_in,
                              void* d_out, int out_size)
{
    (void)in_sizes; (void)n_in; (void)out_size;
    const float* x  = (const float*)d_in[0];
    const float* Wq = (const float*)d_in[1];
    const float* Wk = (const float*)d_in[2];
    const float* Wv = (const float*)d_in[3];
    const float* Wo = (const float*)d_in[4];
    const float* wf = (const float*)d_in[5];
    const float* wp = (const float*)d_in[6];
    float* out = (float*)d_out;

    float *Qp, *Kp, *Vp, *Ap;
    cudaGetSymbolAddress((void**)&Qp, g_Q);
    cudaGetSymbolAddress((void**)&Kp, g_K);
    cudaGetSymbolAddress((void**)&Vp, g_V);
    cudaGetSymbolAddress((void**)&Ap, g_att);

    dim3 ggrid(8, 64);   // (N/64, M/128)

    gemm_tc<<<ggrid, 256>>>(x, Wq, Qp, 1);
    gemm_tc<<<ggrid, 256>>>(x, Wk, Kp, 1);
    gemm_tc<<<ggrid, 256>>>(x, Wv, Vp, 1);

    cudaFuncSetAttribute(wave_attn_tc, cudaFuncAttributeMaxDynamicSharedMemorySize, SMEM_ATTN);
    wave_attn_tc<<<dim3(32, 32), 128, SMEM_ATTN>>>(wf, wp);

    gemm_tc<<<ggrid, 256>>>(Ap, Wo, out, 0);
}

// round 6
// speedup vs baseline: 4.7815x; 1.0205x over previous
#include <cuda_runtime.h>
#include <math.h>

#define NB   4
#define NL   2048
#define ND   512
#define NH   8
#define NDK  64
#define NM   (NB*NL)   /* 8192 */

// Scratch (static __device__ arrays — allocation-free per harness rules)
__device__ float g_Q[NM*ND];    // (B,H,L,dk)
__device__ float g_K[NM*ND];    // (B,H,L,dk)
__device__ float g_V[NM*ND];    // (B,H,L,dk)
__device__ float g_att[NM*ND];  // (B,L,D)

// ---------------------------------------------------------------------------
// TF32 helpers
// ---------------------------------------------------------------------------
__device__ __forceinline__ unsigned f2tf(float f) {
    unsigned u;
    asm("cvt.rna.tf32.f32 %0, %1;" : "=r"(u) : "f"(f));
    return u;
}

// D(16x8) += A(16x8) * B(8x8), tf32 inputs, fp32 accumulate.
// Lane mapping (g = lane>>2, t = lane&3):
//  A: a0=(g,t) a1=(g+8,t) a2=(g,t+4) a3=(g+8,t+4)   [row, k]
//  B: b0=(t,g) b1=(t+4,g)                            [k, n]
//  D: c0=(g,2t) c1=(g,2t+1) c2=(g+8,2t) c3=(g+8,2t+1)
__device__ __forceinline__ void mma8(float* d, const unsigned* a, const unsigned* b) {
    asm volatile("mma.sync.aligned.m16n8k8.row.col.f32.tf32.tf32.f32 "
                 "{%0,%1,%2,%3}, {%4,%5,%6,%7}, {%8,%9}, {%0,%1,%2,%3};"
                 : "+f"(d[0]), "+f"(d[1]), "+f"(d[2]), "+f"(d[3])
                 : "r"(a[0]), "r"(a[1]), "r"(a[2]), "r"(a[3]),
                   "r"(b[0]), "r"(b[1]));
}

// ---------------------------------------------------------------------------
// GEMM (tensor): Y = X @ W^T.  X: (NM,512), W: (512,512), row-major fp32.
// Block tile 256(m) x 64(n), K-chunk 32. 8 warps in 4(m) x 2(n) layout,
// each warp 64x32 (4 m-tiles x 4 n-tiles of m16n8k8).
// mode 0: Y[m*512+n]; mode 1: (B,H,L,dk) scatter, h = blockIdx.x.
// qkv_sel < 0: use W/Y directly. qkv_sel >= 0 handled by wrapper kernel.
// ---------------------------------------------------------------------------
#define XS_ST 36
#define WS_ST 36

__device__ __forceinline__
void gemm_body(const float* __restrict__ X, const float* __restrict__ W,
               float* __restrict__ Y, int mode)
{
    __shared__ float Xs[256 * XS_ST];
    __shared__ float Ws[64 * WS_ST];

    const int tid  = threadIdx.x;
    const int w    = tid >> 5, lane = tid & 31;
    const int g    = lane >> 2, t = lane & 3;
    const int wm   = w & 3, wn = w >> 2;
    const int m0   = blockIdx.y * 256, n0 = blockIdx.x * 64;

    float acc[4][4][4];
    #pragma unroll
    for (int mt = 0; mt < 4; mt++)
        #pragma unroll
        for (int nt = 0; nt < 4; nt++)
            #pragma unroll
            for (int i = 0; i < 4; i++) acc[mt][nt][i] = 0.f;

    for (int k0 = 0; k0 < 512; k0 += 32) {
        // Stage X tile (256x32) as tf32
        #pragma unroll
        for (int i = 0; i < 8; i++) {
            int idx = tid + 256 * i;            // 2048 float4 slots
            int r = idx >> 3, c = (idx & 7) * 4;
            float4 v = *(const float4*)&X[(size_t)(m0 + r) * 512 + k0 + c];
            float4 o = make_float4(__uint_as_float(f2tf(v.x)), __uint_as_float(f2tf(v.y)),
                                   __uint_as_float(f2tf(v.z)), __uint_as_float(f2tf(v.w)));
            *(float4*)&Xs[r * XS_ST + c] = o;
        }
        // Stage W tile (64x32) as tf32
        #pragma unroll
        for (int i = 0; i < 2; i++) {
            int idx = tid + 256 * i;            // 512 float4 slots
            int r = idx >> 3, c = (idx & 7) * 4;
            float4 v = *(const float4*)&W[(size_t)(n0 + r) * 512 + k0 + c];
            float4 o = make_float4(__uint_as_float(f2tf(v.x)), __uint_as_float(f2tf(v.y)),
                                   __uint_as_float(f2tf(v.z)), __uint_as_float(f2tf(v.w)));
            *(float4*)&Ws[r * WS_ST + c] = o;
        }
        __syncthreads();

        #pragma unroll
        for (int ks = 0; ks < 4; ks++) {
            unsigned a[4][4], bb[4][2];
            #pragma unroll
            for (int mt = 0; mt < 4; mt++) {
                const float* p = &Xs[(wm * 64 + mt * 16 + g) * XS_ST + ks * 8 + t];
                a[mt][0] = __float_as_uint(p[0]);
                a[mt][1] = __float_as_uint(p[8 * XS_ST]);
                a[mt][2] = __float_as_uint(p[4]);
                a[mt][3] = __float_as_uint(p[8 * XS_ST + 4]);
            }
            #pragma unroll
            for (int nt = 0; nt < 4; nt++) {
                const float* p = &Ws[(wn * 32 + nt * 8 + g) * WS_ST + ks * 8 + t];
                bb[nt][0] = __float_as_uint(p[0]);
                bb[nt][1] = __float_as_uint(p[4]);
            }
            #pragma unroll
            for (int mt = 0; mt < 4; mt++)
                #pragma unroll
                for (int nt = 0; nt < 4; nt++)
                    mma8(acc[mt][nt], a[mt], bb[nt]);
        }
        __syncthreads();
    }

    // Epilogue
    #pragma unroll
    for (int mt = 0; mt < 4; mt++) {
        int row = m0 + wm * 64 + mt * 16 + g;
        #pragma unroll
        for (int nt = 0; nt < 4; nt++) {
            int off = wn * 32 + nt * 8 + 2 * t;      // 0..63 within n-block
            float2 v0 = make_float2(acc[mt][nt][0], acc[mt][nt][1]);
            float2 v1 = make_float2(acc[mt][nt][2], acc[mt][nt][3]);
            if (mode == 0) {
                float* p = &Y[(size_t)row * 512 + n0 + off];
                *(float2*)p = v0;
                *(float2*)(p + (size_t)8 * 512) = v1;
            } else {
                int b = row >> 11, l = row & 2047, h = blockIdx.x;
                size_t base = ((size_t)((b * 8 + h) * 2048 + l)) * 64 + off;
                *(float2*)&Y[base] = v0;
                *(float2*)&Y[base + (size_t)8 * 64] = v1;
            }
        }
    }
}

// Fused Q/K/V projection: gridDim.z = 3 selects the weight + destination.
__global__ __launch_bounds__(256)
void gemm_qkv(const float* __restrict__ X,
              const float* __restrict__ Wq, const float* __restrict__ Wk,
              const float* __restrict__ Wv,
              float* __restrict__ Qp, float* __restrict__ Kp, float* __restrict__ Vp)
{
    const float* W = (blockIdx.z == 0) ? Wq : (blockIdx.z == 1) ? Wk : Wv;
    float*       Y = (blockIdx.z == 0) ? Qp : (blockIdx.z == 1) ? Kp : Vp;
    gemm_body(X, W, Y, 1);
}

__global__ __launch_bounds__(256)
void gemm_out(const float* __restrict__ X, const float* __restrict__ W,
              float* __restrict__ Y)
{
    gemm_body(X, W, Y, 0);
}

// ---------------------------------------------------------------------------
// Wave attention (tensor): 128 q-rows per block, 4 warps (32 rows each as
// 2 m-tiles), stream 64-key tiles; S=QK^T and O+=PV via tf32 mma; online
// softmax fp32. B-fragments (Ks/Vs) shared across both m-tiles.
// Smem: Ks[64][68], Vs[64][72], Ps[128][68], wave[2048]  (78848 B)
// ---------------------------------------------------------------------------
#define KS_ST 68
#define VS_ST 72
#define PS_ST 68
#define SM_V    (64 * KS_ST)
#define SM_P    (SM_V + 64 * VS_ST)
#define SM_WAVE (SM_P + 128 * PS_ST)
#define SMEM_ATTN ((SM_WAVE + 2048) * 4)

__global__ __launch_bounds__(128, 1)
void wave_attn_tc(const float* __restrict__ wfreq, const float* __restrict__ wphase)
{
    extern __shared__ float sm[];
    float* Ks = sm;
    float* Vs = sm + SM_V;
    float* Ps = sm + SM_P;
    float* Wv = sm + SM_WAVE;

    const int tid = threadIdx.x;
    const int w   = tid >> 5, lane = tid & 31;
    const int g   = lane >> 2, t = lane & 3;
    const int bh  = blockIdx.y, b = bh >> 3, h = bh & 7;
    const int q0  = blockIdx.x * 128;

    const float* Qg = g_Q + ((size_t)bh * NL + q0) * NDK;
    const float* Kg = g_K + (size_t)bh * NL * NDK;
    const float* Vg = g_V + (size_t)bh * NL * NDK;

    // Wave table (once per block)
    {
        const float f = wfreq[h], ph = wphase[h];
        const float TWO_PI = 6.28318530717958647692f;
        for (int j = tid; j < NL; j += 128)
            Wv[j] = cosf(TWO_PI * f * (float)j + ph);
    }

    // Stage Q tile (128x64, scaled by dk^-1/2) into Ps, lift A-fragments
    #pragma unroll
    for (int i = 0; i < 16; i++) {
        int idx = tid + 128 * i;             // 2048 float4 slots
        int r = idx >> 4, c = (idx & 15) * 4;
        float4 v = *(const float4*)&Qg[r * 64 + c];
        v.x *= 0.125f; v.y *= 0.125f; v.z *= 0.125f; v.w *= 0.125f;
        *(float4*)&Ps[r * PS_ST + c] = v;
    }
    __syncthreads();

    unsigned Qa[2][8][4];
    #pragma unroll
    for (int mt = 0; mt < 2; mt++)
        #pragma unroll
        for (int ks = 0; ks < 8; ks++) {
            const float* p = &Ps[(w * 32 + mt * 16 + g) * PS_ST + ks * 8 + t];
            Qa[mt][ks][0] = f2tf(p[0]);
            Qa[mt][ks][1] = f2tf(p[8 * PS_ST]);
            Qa[mt][ks][2] = f2tf(p[4]);
            Qa[mt][ks][3] = f2tf(p[8 * PS_ST + 4]);
        }
    __syncthreads();   // done with Ps as Q staging

    float Oc[2][8][4];
    #pragma unroll
    for (int mt = 0; mt < 2; mt++)
        #pragma unroll
        for (int nt = 0; nt < 8; nt++)
            #pragma unroll
            for (int i = 0; i < 4; i++) Oc[mt][nt][i] = 0.f;
    float mA[2] = {-1e30f, -1e30f}, mB[2] = {-1e30f, -1e30f};
    float lA[2] = {0.f, 0.f},       lB[2] = {0.f, 0.f};

    for (int kt = 0; kt < 32; kt++) {
        // Stage K and V tiles (tf32)
        #pragma unroll
        for (int i = 0; i < 8; i++) {
            int idx = tid + 128 * i;
            int r = idx >> 4, c = (idx & 15) * 4;
            float4 kv = *(const float4*)&Kg[(size_t)(kt * 64 + r) * 64 + c];
            float4 vv = *(const float4*)&Vg[(size_t)(kt * 64 + r) * 64 + c];
            float4 ko = make_float4(__uint_as_float(f2tf(kv.x)), __uint_as_float(f2tf(kv.y)),
                                    __uint_as_float(f2tf(kv.z)), __uint_as_float(f2tf(kv.w)));
            float4 vo = make_float4(__uint_as_float(f2tf(vv.x)), __uint_as_float(f2tf(vv.y)),
                                    __uint_as_float(f2tf(vv.z)), __uint_as_float(f2tf(vv.w)));
            *(float4*)&Ks[r * KS_ST + c] = ko;
            *(float4*)&Vs[r * VS_ST + c] = vo;
        }
        __syncthreads();

        // S = Q @ K^T : both m-tiles share each B-fragment load
        float Sc[2][8][4];
        #pragma unroll
        for (int mt = 0; mt < 2; mt++)
            #pragma unroll
            for (int nt = 0; nt < 8; nt++)
                #pragma unroll
                for (int i = 0; i < 4; i++) Sc[mt][nt][i] = 0.f;
        #pragma unroll
        for (int ks = 0; ks < 8; ks++) {
            #pragma unroll
            for (int nt = 0; nt < 8; nt++) {
                unsigned bb[2];
                const float* p = &Ks[(nt * 8 + g) * KS_ST + ks * 8 + t];
                bb[0] = __float_as_uint(p[0]);
                bb[1] = __float_as_uint(p[4]);
                mma8(Sc[0][nt], Qa[0][ks], bb);
                mma8(Sc[1][nt], Qa[1][ks], bb);
            }
        }

        // Wave modulation + online softmax per m-tile
        #pragma unroll
        for (int mt = 0; mt < 2; mt++) {
            float nmA = mA[mt], nmB = mB[mt];
            #pragma unroll
            for (int nt = 0; nt < 8; nt++) {
                int col = kt * 64 + nt * 8 + 2 * t;
                float w0 = Wv[col], w1 = Wv[col + 1];
                Sc[mt][nt][0] *= w0; Sc[mt][nt][1] *= w1;
                Sc[mt][nt][2] *= w0; Sc[mt][nt][3] *= w1;
                nmA = fmaxf(nmA, fmaxf(Sc[mt][nt][0], Sc[mt][nt][1]));
                nmB = fmaxf(nmB, fmaxf(Sc[mt][nt][2], Sc[mt][nt][3]));
            }
            nmA = fmaxf(nmA, __shfl_xor_sync(0xffffffffu, nmA, 1));
            nmB = fmaxf(nmB, __shfl_xor_sync(0xffffffffu, nmB, 1));
            nmA = fmaxf(nmA, __shfl_xor_sync(0xffffffffu, nmA, 2));
            nmB = fmaxf(nmB, __shfl_xor_sync(0xffffffffu, nmB, 2));

            float scA = __expf(mA[mt] - nmA), scB = __expf(mB[mt] - nmB);
            mA[mt] = nmA; mB[mt] = nmB;

            const int rb = w * 32 + mt * 16 + g;
            float psA = 0.f, psB = 0.f;
            #pragma unroll
            for (int nt = 0; nt < 8; nt++) {
                float p0 = __expf(Sc[mt][nt][0] - nmA);
                float p1 = __expf(Sc[mt][nt][1] - nmA);
                float p2 = __expf(Sc[mt][nt][2] - nmB);
                float p3 = __expf(Sc[mt][nt][3] - nmB);
                psA += p0 + p1; psB += p2 + p3;
                int cb = nt * 8 + 2 * t;
                Ps[rb * PS_ST + cb]           = __uint_as_float(f2tf(p0));
                Ps[rb * PS_ST + cb + 1]       = __uint_as_float(f2tf(p1));
                Ps[(rb + 8) * PS_ST + cb]     = __uint_as_float(f2tf(p2));
                Ps[(rb + 8) * PS_ST + cb + 1] = __uint_as_float(f2tf(p3));
            }
            psA += __shfl_xor_sync(0xffffffffu, psA, 1);
            psB += __shfl_xor_sync(0xffffffffu, psB, 1);
            psA += __shfl_xor_sync(0xffffffffu, psA, 2);
            psB += __shfl_xor_sync(0xffffffffu, psB, 2);
            lA[mt] = lA[mt] * scA + psA;
            lB[mt] = lB[mt] * scB + psB;

            #pragma unroll
            for (int nt = 0; nt < 8; nt++) {
                Oc[mt][nt][0] *= scA; Oc[mt][nt][1] *= scA;
                Oc[mt][nt][2] *= scB; Oc[mt][nt][3] *= scB;
            }
        }
        __syncwarp();   // P rows w*32..w*32+31 are warp-private

        // O += P @ V : both m-tiles share each V B-fragment load
        #pragma unroll
        for (int ks = 0; ks < 8; ks++) {
            unsigned pa[2][4];
            #pragma unroll
            for (int mt = 0; mt < 2; mt++) {
                const float* pp = &Ps[(w * 32 + mt * 16 + g) * PS_ST + ks * 8 + t];
                pa[mt][0] = __float_as_uint(pp[0]);
                pa[mt][1] = __float_as_uint(pp[8 * PS_ST]);
                pa[mt][2] = __float_as_uint(pp[4]);
                pa[mt][3] = __float_as_uint(pp[8 * PS_ST + 4]);
            }
            #pragma unroll
            for (int nt = 0; nt < 8; nt++) {
                unsigned bb[2];
                const float* vp = &Vs[(ks * 8 + t) * VS_ST + nt * 8 + g];
                bb[0] = __float_as_uint(vp[0]);
                bb[1] = __float_as_uint(vp[4 * VS_ST]);
                mma8(Oc[0][nt], pa[0], bb);
                mma8(Oc[1][nt], pa[1], bb);
            }
        }
        __syncthreads();   // before next tile overwrites Ks/Vs
    }

    // Epilogue: normalize, write (B,L,D)
    #pragma unroll
    for (int mt = 0; mt < 2; mt++) {
        float iA = 1.f / lA[mt], iB = 1.f / lB[mt];
        int rowA = q0 + w * 32 + mt * 16 + g;
        size_t baseA = ((size_t)b * NL + rowA) * ND + h * NDK;
        size_t baseB = baseA + (size_t)8 * ND;
        #pragma unroll
        for (int nt = 0; nt < 8; nt++) {
            int cb = nt * 8 + 2 * t;
            *(float2*)&g_att[baseA + cb] =
                make_float2(Oc[mt][nt][0] * iA, Oc[mt][nt][1] * iA);
            *(float2*)&g_att[baseB + cb] =
                make_float2(Oc[mt][nt][2] * iB, Oc[mt][nt][3] * iB);
        }
    }
}

// ---------------------------------------------------------------------------
extern "C" void kernel_launch(void* const* d_in, const int* in_sizes, int n_in,
                              void* d_out, int out_size)
{
    (void)in_sizes; (void)n_in; (void)out_size;
    const float* x  = (const float*)d_in[0];
    const float* Wq = (const float*)d_in[1];
    const float* Wk = (const float*)d_in[2];
    const float* Wv = (const float*)d_in[3];
    const float* Wo = (const float*)d_in[4];
    const float* wf = (const float*)d_in[5];
    const float* wp = (const float*)d_in[6];
    float* out = (float*)d_out;

    float *Qp, *Kp, *Vp, *Ap;
    cudaGetSymbolAddress((void**)&Qp, g_Q);
    cudaGetSymbolAddress((void**)&Kp, g_K);
    cudaGetSymbolAddress((void**)&Vp, g_V);
    cudaGetSymbolAddress((void**)&Ap, g_att);

    dim3 ggrid(8, 32, 3);   // (N/64, M/256, qkv)
    gemm_qkv<<<ggrid, 256>>>(x, Wq, Wk, Wv, Qp, Kp, Vp);

    cudaFuncSetAttribute(wave_attn_tc, cudaFuncAttributeMaxDynamicSharedMemorySize, SMEM_ATTN);
    wave_attn_tc<<<dim3(16, 32), 128, SMEM_ATTN>>>(wf, wp);

    gemm_out<<<dim3(8, 32), 256>>>(Ap, Wo, out);
}

// round 7
// speedup vs baseline: 5.7461x; 1.2018x over previous
#include <cuda_runtime.h>
#include <math.h>

#define NB   4
#define NL   2048
#define ND   512
#define NH   8
#define NDK  64
#define NM   (NB*NL)   /* 8192 */

// Scratch (static __device__ arrays — allocation-free per harness rules)
__device__ float g_Q[NM*ND];    // (B,H,L,dk)
__device__ float g_K[NM*ND];    // (B,H,L,dk)
__device__ float g_V[NM*ND];    // (B,H,L,dk)
__device__ float g_att[NM*ND];  // (B,L,D)

// ---------------------------------------------------------------------------
// TF32 / cp.async helpers
// ---------------------------------------------------------------------------
__device__ __forceinline__ unsigned f2tf(float f) {
    unsigned u;
    asm("cvt.rna.tf32.f32 %0, %1;" : "=r"(u) : "f"(f));
    return u;
}

__device__ __forceinline__ void cpa16(float* sptr, const float* gptr) {
    unsigned s = (unsigned)__cvta_generic_to_shared(sptr);
    asm volatile("cp.async.cg.shared.global [%0], [%1], 16;" :: "r"(s), "l"(gptr));
}
__device__ __forceinline__ void cpa_commit() {
    asm volatile("cp.async.commit_group;" ::: "memory");
}
__device__ __forceinline__ void cpa_wait1() {
    asm volatile("cp.async.wait_group 1;" ::: "memory");
}
__device__ __forceinline__ void cpa_wait0() {
    asm volatile("cp.async.wait_group 0;" ::: "memory");
}

// D(16x8) += A(16x8) * B(8x8), tf32 inputs, fp32 accumulate.
// Lane mapping (g = lane>>2, t = lane&3):
//  A: a0=(g,t) a1=(g+8,t) a2=(g,t+4) a3=(g+8,t+4)   [row, k]
//  B: b0=(t,g) b1=(t+4,g)                            [k, n]
//  D: c0=(g,2t) c1=(g,2t+1) c2=(g+8,2t) c3=(g+8,2t+1)
__device__ __forceinline__ void mma8(float* d, const unsigned* a, const unsigned* b) {
    asm volatile("mma.sync.aligned.m16n8k8.row.col.f32.tf32.tf32.f32 "
                 "{%0,%1,%2,%3}, {%4,%5,%6,%7}, {%8,%9}, {%0,%1,%2,%3};"
                 : "+f"(d[0]), "+f"(d[1]), "+f"(d[2]), "+f"(d[3])
                 : "r"(a[0]), "r"(a[1]), "r"(a[2]), "r"(a[3]),
                   "r"(b[0]), "r"(b[1]));
}

// ---------------------------------------------------------------------------
// GEMM (tensor, cp.async double-buffered): Y = X @ W^T.
// X: (NM,512), W: (512,512), row-major fp32. Block tile (MT*64)m x 64n,
// K-chunk 32, 8 warps in 4(m) x 2(n), warp tile (MT*16) x 32.
// Smem holds raw fp32; tf32 conversion (cvt.rna) at fragment-load time —
// numerically identical to converting at staging time.
// mode 0: Y[m*512+n]; mode 1: (B,H,L,dk) scatter, h = blockIdx.x.
// ---------------------------------------------------------------------------
#define XS_ST 36
#define WS_ST 36

template<int MT>
__device__ __forceinline__
void gemm_body(const float* __restrict__ X, const float* __restrict__ W,
               float* __restrict__ Y, int mode)
{
    constexpr int BM = MT * 64;
    extern __shared__ float smem[];
    float* Xs0 = smem;                       // 2 x BM*XS_ST
    float* Ws0 = smem + 2 * BM * XS_ST;      // 2 x 64*WS_ST

    const int tid  = threadIdx.x;
    const int w    = tid >> 5, lane = tid & 31;
    const int g    = lane >> 2, t = lane & 3;
    const int wm   = w & 3, wn = w >> 2;
    const int m0   = blockIdx.y * BM, n0 = blockIdx.x * 64;

    float acc[MT][4][4];
    #pragma unroll
    for (int mt = 0; mt < MT; mt++)
        #pragma unroll
        for (int nt = 0; nt < 4; nt++)
            #pragma unroll
            for (int i = 0; i < 4; i++) acc[mt][nt][i] = 0.f;

    // async stage of one K-chunk into buffer `buf`
    auto stage = [&](int k0, int buf) {
        float* Xs = Xs0 + buf * BM * XS_ST;
        float* Ws = Ws0 + buf * 64 * WS_ST;
        #pragma unroll
        for (int i = 0; i < MT * 2; i++) {           // BM*8 16B-chunks / 256 thr
            int idx = tid + 256 * i;
            int r = idx >> 3, c = (idx & 7) * 4;
            cpa16(&Xs[r * XS_ST + c], &X[(size_t)(m0 + r) * 512 + k0 + c]);
        }
        #pragma unroll
        for (int i = 0; i < 2; i++) {                // 512 chunks / 256 thr
            int idx = tid + 256 * i;
            int r = idx >> 3, c = (idx & 7) * 4;
            cpa16(&Ws[r * WS_ST + c], &W[(size_t)(n0 + r) * 512 + k0 + c]);
        }
        cpa_commit();
    };

    stage(0, 0);
    for (int kc = 0; kc < 16; kc++) {
        if (kc + 1 < 16) { stage((kc + 1) * 32, (kc + 1) & 1); cpa_wait1(); }
        else             { cpa_wait0(); }
        __syncthreads();

        const float* Xs = Xs0 + (kc & 1) * BM * XS_ST;
        const float* Ws = Ws0 + (kc & 1) * 64 * WS_ST;

        #pragma unroll
        for (int ks = 0; ks < 4; ks++) {
            unsigned a[MT][4], bb[4][2];
            #pragma unroll
            for (int mt = 0; mt < MT; mt++) {
                const float* p = &Xs[(wm * (MT * 16) + mt * 16 + g) * XS_ST + ks * 8 + t];
                a[mt][0] = f2tf(p[0]);
                a[mt][1] = f2tf(p[8 * XS_ST]);
                a[mt][2] = f2tf(p[4]);
                a[mt][3] = f2tf(p[8 * XS_ST + 4]);
            }
            #pragma unroll
            for (int nt = 0; nt < 4; nt++) {
                const float* p = &Ws[(wn * 32 + nt * 8 + g) * WS_ST + ks * 8 + t];
                bb[nt][0] = f2tf(p[0]);
                bb[nt][1] = f2tf(p[4]);
            }
            #pragma unroll
            for (int mt = 0; mt < MT; mt++)
                #pragma unroll
                for (int nt = 0; nt < 4; nt++)
                    mma8(acc[mt][nt], a[mt], bb[nt]);
        }
        __syncthreads();
    }

    // Epilogue
    #pragma unroll
    for (int mt = 0; mt < MT; mt++) {
        int row = m0 + wm * (MT * 16) + mt * 16 + g;
        #pragma unroll
        for (int nt = 0; nt < 4; nt++) {
            int off = wn * 32 + nt * 8 + 2 * t;      // 0..63 within n-block
            float2 v0 = make_float2(acc[mt][nt][0], acc[mt][nt][1]);
            float2 v1 = make_float2(acc[mt][nt][2], acc[mt][nt][3]);
            if (mode == 0) {
                float* p = &Y[(size_t)row * 512 + n0 + off];
                *(float2*)p = v0;
                *(float2*)(p + (size_t)8 * 512) = v1;
            } else {
                int b = row >> 11, l = row & 2047, h = blockIdx.x;
                size_t base = ((size_t)((b * 8 + h) * 2048 + l)) * 64 + off;
                *(float2*)&Y[base] = v0;
                *(float2*)&Y[base + (size_t)8 * 64] = v1;
            }
        }
    }
}

#define SMEM_GEMM4 ((2 * 256 * XS_ST + 2 * 64 * WS_ST) * 4)   /* 92160 B */
#define SMEM_GEMM2 ((2 * 128 * XS_ST + 2 * 64 * WS_ST) * 4)   /* 55296 B */

// Fused Q/K/V projection: gridDim.z = 3 selects the weight + destination.
__global__ __launch_bounds__(256)
void gemm_qkv(const float* __restrict__ X,
              const float* __restrict__ Wq, const float* __restrict__ Wk,
              const float* __restrict__ Wv,
              float* __restrict__ Qp, float* __restrict__ Kp, float* __restrict__ Vp)
{
    const float* W = (blockIdx.z == 0) ? Wq : (blockIdx.z == 1) ? Wk : Wv;
    float*       Y = (blockIdx.z == 0) ? Qp : (blockIdx.z == 1) ? Kp : Vp;
    gemm_body<4>(X, W, Y, 1);
}

__global__ __launch_bounds__(256)
void gemm_out(const float* __restrict__ X, const float* __restrict__ W,
              float* __restrict__ Y)
{
    gemm_body<2>(X, W, Y, 0);
}

// ---------------------------------------------------------------------------
// Wave attention (tensor, cp.async double-buffered K/V): 128 q-rows per
// block, 4 warps (32 rows each as 2 m-tiles), stream 64-key tiles;
// S=QK^T and O+=PV via tf32 mma; online softmax fp32.
// Smem floats: Ks[2][64*68], Vs[2][64*72], Ps[128*68], wave[2048] = 114688 B
// ---------------------------------------------------------------------------
#define KS_ST 68
#define VS_ST 72
#define PS_ST 68
#define SM_VS   (2 * 64 * KS_ST)
#define SM_PS   (SM_VS + 2 * 64 * VS_ST)
#define SM_WAVE (SM_PS + 128 * PS_ST)
#define SMEM_ATTN ((SM_WAVE + 2048) * 4)

__global__ __launch_bounds__(128, 1)
void wave_attn_tc(const float* __restrict__ wfreq, const float* __restrict__ wphase)
{
    extern __shared__ float sm[];
    float* Ks0 = sm;
    float* Vs0 = sm + SM_VS;
    float* Ps  = sm + SM_PS;
    float* Wv  = sm + SM_WAVE;

    const int tid = threadIdx.x;
    const int w   = tid >> 5, lane = tid & 31;
    const int g   = lane >> 2, t = lane & 3;
    const int bh  = blockIdx.y, b = bh >> 3, h = bh & 7;
    const int q0  = blockIdx.x * 128;

    const float* Qg = g_Q + ((size_t)bh * NL + q0) * NDK;
    const float* Kg = g_K + (size_t)bh * NL * NDK;
    const float* Vg = g_V + (size_t)bh * NL * NDK;

    // async stage of K/V tile kt into buffer `buf` (raw fp32)
    auto stage_kv = [&](int kt, int buf) {
        float* Ksb = Ks0 + buf * 64 * KS_ST;
        float* Vsb = Vs0 + buf * 64 * VS_ST;
        #pragma unroll
        for (int i = 0; i < 8; i++) {
            int idx = tid + 128 * i;
            int r = idx >> 4, c = (idx & 15) * 4;
            const float* gk = &Kg[(size_t)(kt * 64 + r) * 64 + c];
            const float* gv = &Vg[(size_t)(kt * 64 + r) * 64 + c];
            cpa16(&Ksb[r * KS_ST + c], gk);
            cpa16(&Vsb[r * VS_ST + c], gv);
        }
        cpa_commit();
    };

    stage_kv(0, 0);   // tile 0 in flight while we do wave table + Q staging

    // Wave table (once per block)
    {
        const float f = wfreq[h], ph = wphase[h];
        const float TWO_PI = 6.28318530717958647692f;
        for (int j = tid; j < NL; j += 128)
            Wv[j] = cosf(TWO_PI * f * (float)j + ph);
    }

    // Stage Q tile (128x64, scaled by dk^-1/2) into Ps, lift A-fragments
    #pragma unroll
    for (int i = 0; i < 16; i++) {
        int idx = tid + 128 * i;             // 2048 float4 slots
        int r = idx >> 4, c = (idx & 15) * 4;
        float4 v = *(const float4*)&Qg[r * 64 + c];
        v.x *= 0.125f; v.y *= 0.125f; v.z *= 0.125f; v.w *= 0.125f;
        *(float4*)&Ps[r * PS_ST + c] = v;
    }
    __syncthreads();

    unsigned Qa[2][8][4];
    #pragma unroll
    for (int mt = 0; mt < 2; mt++)
        #pragma unroll
        for (int ks = 0; ks < 8; ks++) {
            const float* p = &Ps[(w * 32 + mt * 16 + g) * PS_ST + ks * 8 + t];
            Qa[mt][ks][0] = f2tf(p[0]);
            Qa[mt][ks][1] = f2tf(p[8 * PS_ST]);
            Qa[mt][ks][2] = f2tf(p[4]);
            Qa[mt][ks][3] = f2tf(p[8 * PS_ST + 4]);
        }
    __syncthreads();   // done with Ps as Q staging

    float Oc[2][8][4];
    #pragma unroll
    for (int mt = 0; mt < 2; mt++)
        #pragma unroll
        for (int nt = 0; nt < 8; nt++)
            #pragma unroll
            for (int i = 0; i < 4; i++) Oc[mt][nt][i] = 0.f;
    float mA[2] = {-1e30f, -1e30f}, mB[2] = {-1e30f, -1e30f};
    float lA[2] = {0.f, 0.f},       lB[2] = {0.f, 0.f};

    for (int kt = 0; kt < 32; kt++) {
        if (kt + 1 < 32) { stage_kv(kt + 1, (kt + 1) & 1); cpa_wait1(); }
        else             { cpa_wait0(); }
        __syncthreads();

        const float* Ksb = Ks0 + (kt & 1) * 64 * KS_ST;
        const float* Vsb = Vs0 + (kt & 1) * 64 * VS_ST;

        // S = Q @ K^T : both m-tiles share each B-fragment load (tf32 at read)
        float Sc[2][8][4];
        #pragma unroll
        for (int mt = 0; mt < 2; mt++)
            #pragma unroll
            for (int nt = 0; nt < 8; nt++)
                #pragma unroll
                for (int i = 0; i < 4; i++) Sc[mt][nt][i] = 0.f;
        #pragma unroll
        for (int ks = 0; ks < 8; ks++) {
            #pragma unroll
            for (int nt = 0; nt < 8; nt++) {
                unsigned bb[2];
                const float* p = &Ksb[(nt * 8 + g) * KS_ST + ks * 8 + t];
                bb[0] = f2tf(p[0]);
                bb[1] = f2tf(p[4]);
                mma8(Sc[0][nt], Qa[0][ks], bb);
                mma8(Sc[1][nt], Qa[1][ks], bb);
            }
        }

        // Wave modulation + online softmax per m-tile
        #pragma unroll
        for (int mt = 0; mt < 2; mt++) {
            float nmA = mA[mt], nmB = mB[mt];
            #pragma unroll
            for (int nt = 0; nt < 8; nt++) {
                int col = kt * 64 + nt * 8 + 2 * t;
                float w0 = Wv[col], w1 = Wv[col + 1];
                Sc[mt][nt][0] *= w0; Sc[mt][nt][1] *= w1;
                Sc[mt][nt][2] *= w0; Sc[mt][nt][3] *= w1;
                nmA = fmaxf(nmA, fmaxf(Sc[mt][nt][0], Sc[mt][nt][1]));
                nmB = fmaxf(nmB, fmaxf(Sc[mt][nt][2], Sc[mt][nt][3]));
            }
            nmA = fmaxf(nmA, __shfl_xor_sync(0xffffffffu, nmA, 1));
            nmB = fmaxf(nmB, __shfl_xor_sync(0xffffffffu, nmB, 1));
            nmA = fmaxf(nmA, __shfl_xor_sync(0xffffffffu, nmA, 2));
            nmB = fmaxf(nmB, __shfl_xor_sync(0xffffffffu, nmB, 2));

            float scA = __expf(mA[mt] - nmA), scB = __expf(mB[mt] - nmB);
            mA[mt] = nmA; mB[mt] = nmB;

            const int rb = w * 32 + mt * 16 + g;
            float psA = 0.f, psB = 0.f;
            #pragma unroll
            for (int nt = 0; nt < 8; nt++) {
                float p0 = __expf(Sc[mt][nt][0] - nmA);
                float p1 = __expf(Sc[mt][nt][1] - nmA);
                float p2 = __expf(Sc[mt][nt][2] - nmB);
                float p3 = __expf(Sc[mt][nt][3] - nmB);
                psA += p0 + p1; psB += p2 + p3;
                int cb = nt * 8 + 2 * t;
                Ps[rb * PS_ST + cb]           = __uint_as_float(f2tf(p0));
                Ps[rb * PS_ST + cb + 1]       = __uint_as_float(f2tf(p1));
                Ps[(rb + 8) * PS_ST + cb]     = __uint_as_float(f2tf(p2));
                Ps[(rb + 8) * PS_ST + cb + 1] = __uint_as_float(f2tf(p3));
            }
            psA += __shfl_xor_sync(0xffffffffu, psA, 1);
            psB += __shfl_xor_sync(0xffffffffu, psB, 1);
            psA += __shfl_xor_sync(0xffffffffu, psA, 2);
            psB += __shfl_xor_sync(0xffffffffu, psB, 2);
            lA[mt] = lA[mt] * scA + psA;
            lB[mt] = lB[mt] * scB + psB;

            #pragma unroll
            for (int nt = 0; nt < 8; nt++) {
                Oc[mt][nt][0] *= scA; Oc[mt][nt][1] *= scA;
                Oc[mt][nt][2] *= scB; Oc[mt][nt][3] *= scB;
            }
        }
        __syncwarp();   // P rows w*32..w*32+31 are warp-private

        // O += P @ V : both m-tiles share each V B-fragment load
        #pragma unroll
        for (int ks = 0; ks < 8; ks++) {
            unsigned pa[2][4];
            #pragma unroll
            for (int mt = 0; mt < 2; mt++) {
                const float* pp = &Ps[(w * 32 + mt * 16 + g) * PS_ST + ks * 8 + t];
                pa[mt][0] = __float_as_uint(pp[0]);
                pa[mt][1] = __float_as_uint(pp[8 * PS_ST]);
                pa[mt][2] = __float_as_uint(pp[4]);
                pa[mt][3] = __float_as_uint(pp[8 * PS_ST + 4]);
            }
            #pragma unroll
            for (int nt = 0; nt < 8; nt++) {
                unsigned bb[2];
                const float* vp = &Vsb[(ks * 8 + t) * VS_ST + nt * 8 + g];
                bb[0] = f2tf(vp[0]);
                bb[1] = f2tf(vp[4 * VS_ST]);
                mma8(Oc[0][nt], pa[0], bb);
                mma8(Oc[1][nt], pa[1], bb);
            }
        }
        __syncthreads();   // before next tile's cp.async overwrites this buffer
    }

    // Epilogue: normalize, write (B,L,D)
    #pragma unroll
    for (int mt = 0; mt < 2; mt++) {
        float iA = 1.f / lA[mt], iB = 1.f / lB[mt];
        int rowA = q0 + w * 32 + mt * 16 + g;
        size_t baseA = ((size_t)b * NL + rowA) * ND + h * NDK;
        size_t baseB = baseA + (size_t)8 * ND;
        #pragma unroll
        for (int nt = 0; nt < 8; nt++) {
            int cb = nt * 8 + 2 * t;
            *(float2*)&g_att[baseA + cb] =
                make_float2(Oc[mt][nt][0] * iA, Oc[mt][nt][1] * iA);
            *(float2*)&g_att[baseB + cb] =
                make_float2(Oc[mt][nt][2] * iB, Oc[mt][nt][3] * iB);
        }
    }
}

// ---------------------------------------------------------------------------
extern "C" void kernel_launch(void* const* d_in, const int* in_sizes, int n_in,
                              void* d_out, int out_size)
{
    (void)in_sizes; (void)n_in; (void)out_size;
    const float* x  = (const float*)d_in[0];
    const float* Wq = (const float*)d_in[1];
    const float* Wk = (const float*)d_in[2];
    const float* Wv = (const float*)d_in[3];
    const float* Wo = (const float*)d_in[4];
    const float* wf = (const float*)d_in[5];
    const float* wp = (const float*)d_in[6];
    float* out = (float*)d_out;

    float *Qp, *Kp, *Vp, *Ap;
    cudaGetSymbolAddress((void**)&Qp, g_Q);
    cudaGetSymbolAddress((void**)&Kp, g_K);
    cudaGetSymbolAddress((void**)&Vp, g_V);
    cudaGetSymbolAddress((void**)&Ap, g_att);

    cudaFuncSetAttribute(gemm_qkv, cudaFuncAttributeMaxDynamicSharedMemorySize, SMEM_GEMM4);
    cudaFuncSetAttribute(gemm_out, cudaFuncAttributeMaxDynamicSharedMemorySize, SMEM_GEMM2);
    cudaFuncSetAttribute(wave_attn_tc, cudaFuncAttributeMaxDynamicSharedMemorySize, SMEM_ATTN);

    dim3 ggrid(8, 32, 3);   // (N/64, M/256, qkv)
    gemm_qkv<<<ggrid, 256, SMEM_GEMM4>>>(x, Wq, Wk, Wv, Qp, Kp, Vp);

    wave_attn_tc<<<dim3(16, 32), 128, SMEM_ATTN>>>(wf, wp);

    gemm_out<<<dim3(8, 64), 256, SMEM_GEMM2>>>(Ap, Wo, out);
}